// round 8
// baseline (speedup 1.0000x reference)
#include <cuda_runtime.h>
#include <cuda_fp16.h>
#include <cstdint>

// Problem constants
#define BB 2
#define SS 2048
#define VV 32000
#define HH 512
#define GG 1536
#define LL 3
#define RR (BB*SS)
#define NCH 64
#define CL  (SS/NCH)   // 32
#define KDIM 512

// ---------------- scratch ----------------
__device__ __align__(128) float g_x[RR * HH];
__device__ __align__(128) float g_gates[RR * GG];
__device__ __align__(128) float g_aggF[BB * NCH * HH];
__device__ __align__(128) float g_aggH[BB * NCH * HH];
__device__ __align__(128) int   g_flags[LL * BB * NCH];
__device__ __align__(128) __half g_xn[RR * HH];
__device__ __align__(128) __half g_wsh[LL * GG * HH];
__device__ __align__(128) __half g_fch[(size_t)VV * HH];

// ---------------- helpers ----------------
__device__ __forceinline__ uint32_t smem_u32(const void* p) {
    uint32_t a;
    asm("{ .reg .u64 t; cvta.to.shared.u64 t, %1; cvt.u32.u64 %0, t; }" : "=r"(a) : "l"(p));
    return a;
}
__device__ __forceinline__ void ldsm4(uint32_t* r, uint32_t addr) {
    asm volatile("ldmatrix.sync.aligned.m8n8.x4.shared.b16 {%0,%1,%2,%3}, [%4];"
        : "=r"(r[0]), "=r"(r[1]), "=r"(r[2]), "=r"(r[3]) : "r"(addr));
}
__device__ __forceinline__ void mma16816(float* d, const uint32_t* a, const uint32_t* b) {
    asm volatile("mma.sync.aligned.m16n8k16.row.col.f32.f16.f16.f32 "
        "{%0,%1,%2,%3}, {%4,%5,%6,%7}, {%8,%9}, {%0,%1,%2,%3};"
        : "+f"(d[0]), "+f"(d[1]), "+f"(d[2]), "+f"(d[3])
        : "r"(a[0]), "r"(a[1]), "r"(a[2]), "r"(a[3]), "r"(b[0]), "r"(b[1]));
}
__device__ __forceinline__ void cp16(uint32_t dst, const void* src) {
    asm volatile("cp.async.cg.shared.global [%0], [%1], 16;" :: "r"(dst), "l"(src));
}

// ---------------- fp16 tensor-core GEMM (R6 config: best measured) ----------------
// CTA tile 128x128, 4 warps (2x2), warp tile 64x64, K staged 64, 3-stage cp.async.
#define STB (32 * 1024)
#define NSTAGE 3
#define GSMEM_TOTAL (NSTAGE * STB)

template<bool STREAM>
__global__ __launch_bounds__(128, 2) void gemm_mma(
    const __half* __restrict__ A, const __half* __restrict__ B,
    const float* __restrict__ bias, float* __restrict__ C, int N)
{
    extern __shared__ char smem[];
    const uint32_t sb = smem_u32(smem);
    const int tid = threadIdx.x;
    const int wid = tid >> 5, lane = tid & 31;
    const int m0 = blockIdx.y * 128, n0 = blockIdx.x * 128;
    const int wm = wid & 1, wn = wid >> 1;

    const char* baseA = (const char*)A + (size_t)m0 * (KDIM * 2);
    const char* baseB = (const char*)B + (size_t)n0 * (KDIM * 2);

    float acc[4][8][4];
#pragma unroll
    for (int i = 0; i < 4; i++)
#pragma unroll
        for (int j = 0; j < 8; j++)
#pragma unroll
            for (int q = 0; q < 4; q++) acc[i][j][q] = 0.f;

    auto load_stage = [&](int kc, int buf) {
        const int kb = kc * 128;
        const uint32_t sp = sb + buf * STB;
#pragma unroll
        for (int it = 0; it < 16; it++) {
            int idx = tid + it * 128;
            int r = idx >> 3, c = idx & 7;
            const char* src; uint32_t roff; int lr;
            if (r < 128) { src = baseA; roff = 0;     lr = r; }
            else         { src = baseB; roff = 16384; lr = r - 128; }
            const char* g = src + (size_t)lr * (KDIM * 2) + kb + c * 16;
            uint32_t bo = (uint32_t)(lr * 128 + c * 16);
            bo ^= (bo >> 3) & 0x70;
            cp16(sp + roff + bo, g);
        }
        asm volatile("cp.async.commit_group;" ::: "memory");
    };

    const int quad = lane >> 3, r8 = lane & 7;

    load_stage(0, 0);
    load_stage(1, 1);

    for (int kc = 0; kc < 8; kc++) {
        if (kc < 7) {
            asm volatile("cp.async.wait_group 1;" ::: "memory");
        } else {
            asm volatile("cp.async.wait_group 0;" ::: "memory");
        }
        __syncthreads();

        const uint32_t sp = sb + (kc % NSTAGE) * STB;
#pragma unroll
        for (int ks = 0; ks < 4; ks++) {
            const int colA = ks * 32 + (quad >> 1) * 16;
            const int colB = ks * 32 + (quad & 1) * 16;

            uint32_t af[4][4];
#pragma unroll
            for (int i = 0; i < 4; i++) {
                int row = wm * 64 + i * 16 + r8 + (quad & 1) * 8;
                uint32_t bo = (uint32_t)(row * 128 + colA);
                bo ^= (bo >> 3) & 0x70;
                ldsm4(af[i], sp + bo);
            }
            uint32_t bf[4][4];
#pragma unroll
            for (int j4 = 0; j4 < 4; j4++) {
                int row = wn * 64 + j4 * 16 + r8 + (quad >> 1) * 8;
                uint32_t bo = (uint32_t)(row * 128 + colB);
                bo ^= (bo >> 3) & 0x70;
                ldsm4(bf[j4], sp + 16384 + bo);
            }
#pragma unroll
            for (int i = 0; i < 4; i++)
#pragma unroll
                for (int j = 0; j < 8; j++)
                    mma16816(acc[i][j], af[i], &bf[j >> 1][(j & 1) * 2]);
        }

        if (kc + 2 < 8) load_stage(kc + 2, (kc + 2) % NSTAGE);
    }

    const int tq = lane >> 2, tr = lane & 3;
#pragma unroll
    for (int i = 0; i < 4; i++) {
        int mrow = m0 + wm * 64 + i * 16;
#pragma unroll
        for (int j = 0; j < 8; j++) {
            int col = n0 + wn * 64 + j * 8 + tr * 2;
            float b0 = __ldg(bias + col), b1 = __ldg(bias + col + 1);
            float2 v0 = { acc[i][j][0] + b0, acc[i][j][1] + b1 };
            float2 v1 = { acc[i][j][2] + b0, acc[i][j][3] + b1 };
            float* p0 = C + (size_t)(mrow + tq) * N + col;
            float* p1 = C + (size_t)(mrow + tq + 8) * N + col;
            if (STREAM) { __stcs((float2*)p0, v0); __stcs((float2*)p1, v1); }
            else        { *(float2*)p0 = v0;       *(float2*)p1 = v1; }
        }
    }
}

// ---------------- fp32 -> fp16 convert ----------------
__global__ void convert_kernel(const float* __restrict__ w,
                               __half* __restrict__ o, int n4) {
    int i = blockIdx.x * 256 + threadIdx.x;
    if (i >= n4) return;
    float4 v = __ldg((const float4*)w + i);
    __half2 p0 = { __float2half_rn(v.x), __float2half_rn(v.y) };
    __half2 p1 = { __float2half_rn(v.z), __float2half_rn(v.w) };
    ((__half2*)o)[i * 2] = p0;
    ((__half2*)o)[i * 2 + 1] = p1;
}

// ---------------- flag clear (per launch, before scans) ----------------
__global__ void clear_flags_kernel(int* flags) {
    flags[threadIdx.x] = 0;
}

// ---------------- shared LN tail ----------------
__device__ __forceinline__ void ln_tail(float4* v, float s, float s2, int lane,
                                        const float* __restrict__ w,
                                        const float* __restrict__ bptr, int hasB,
                                        __half* __restrict__ out, size_t rowbase) {
#pragma unroll
    for (int o = 16; o > 0; o >>= 1) {
        s  += __shfl_xor_sync(0xffffffffu, s, o);
        s2 += __shfl_xor_sync(0xffffffffu, s2, o);
    }
    float mean = s * (1.f / HH);
    float var  = s2 * (1.f / HH) - mean * mean;
    float rs = rsqrtf(var + 1e-5f);

    __half2* oh = (__half2*)(out + rowbase);
    const float4* w4 = (const float4*)w;
    const float4* b4 = (const float4*)bptr;
#pragma unroll
    for (int r = 0; r < 4; r++) {
        float4 ww = w4[lane + r * 32];
        float4 o;
        o.x = (v[r].x - mean) * rs * ww.x;
        o.y = (v[r].y - mean) * rs * ww.y;
        o.z = (v[r].z - mean) * rs * ww.z;
        o.w = (v[r].w - mean) * rs * ww.w;
        if (hasB) {
            float4 bb = b4[lane + r * 32];
            o.x += bb.x; o.y += bb.y; o.z += bb.z; o.w += bb.w;
        }
        __half2 p0 = { __float2half_rn(o.x), __float2half_rn(o.y) };
        __half2 p1 = { __float2half_rn(o.z), __float2half_rn(o.w) };
        int e2 = (lane + r * 32) * 2;
        oh[e2] = p0; oh[e2 + 1] = p1;
    }
}

// ---------------- fused embedding gather + LN0 ----------------
__global__ __launch_bounds__(256) void embed_ln_kernel(
    const int* __restrict__ ids, const float* __restrict__ emb,
    float* __restrict__ x, __half* __restrict__ xn,
    const float* __restrict__ w, const float* __restrict__ bptr) {
    int gw = (blockIdx.x * 256 + threadIdx.x) >> 5;
    int lane = threadIdx.x & 31;
    int id = __ldg(ids + gw);
    const float4* src = (const float4*)(emb + (size_t)id * HH);
    float4* xr = (float4*)(x + (size_t)gw * HH);

    float4 v[4];
    float s = 0.f, s2 = 0.f;
#pragma unroll
    for (int r = 0; r < 4; r++) {
        v[r] = src[lane + r * 32];
        xr[lane + r * 32] = v[r];
        s  += v[r].x + v[r].y + v[r].z + v[r].w;
        s2 += v[r].x * v[r].x + v[r].y * v[r].y + v[r].z * v[r].z + v[r].w * v[r].w;
    }
    ln_tail(v, s, s2, lane, w, bptr, 1, xn, (size_t)gw * HH);
}

// ---------------- FUSED single-pass scan: gate math + local scan + cross-chunk
// carry (flag-signaled) + apply + residual + LN, one kernel per layer ----------------
// grid (NCH, BB), 512 threads. smem: SH[CL*HH], SP[CL*HH], SC[HH] = 130KB.
#define SCAN_SMEM ((2 * CL * HH + HH) * 4)

__global__ __launch_bounds__(512) void scan_fused_kernel(
    const float* __restrict__ gates,
    float* __restrict__ x, __half* __restrict__ xn,
    const float* __restrict__ lnw, const float* __restrict__ lnb,
    int hasB, int writeX,
    float* __restrict__ aggF, float* __restrict__ aggH,
    int* __restrict__ flags)
{
    extern __shared__ char smem[];
    float* SH = (float*)smem;            // [CL][HH] local h
    float* SP = SH + CL * HH;            // [CL][HH] local cumprod f
    float* SC = SP + CL * HH;            // [HH] carry per channel

    const int c = threadIdx.x;           // channel
    const int j = blockIdx.x;            // chunk
    const int b = blockIdx.y;            // batch
    const size_t row0 = (size_t)b * SS + (size_t)j * CL;

    // ---- phase 1: local scan (identical math/order to previous gatescan) ----
    float h = 0.f, p = 1.f;
#pragma unroll 4
    for (int t = 0; t < CL; t++) {
        const float* gp = gates + (row0 + t) * GG;
        float fg = gp[c], ig = gp[HH + c], td = gp[2 * HH + c];
        float ea = __expf(-fg), eb = __expf(-ig);
        float inv = __fdividef(1.0f, 2.0f + ea + eb);
        float f = (1.0f + eb) * inv;
        float iv = (1.0f + ea) * inv;
        float g = (td >= 0.f) ? (td + 0.5f) : __fdividef(1.0f, 1.0f + __expf(-td));
        float v = iv * g;
        h = fmaf(f, h, v);
        p *= f;
        SH[t * HH + c] = h;
        SP[t * HH + c] = p;
    }

    // ---- phase 2: publish aggregate, wait predecessors, sequential combine ----
    {
        int ai = (b * NCH + j) * HH + c;
        aggF[ai] = p;
        aggH[ai] = h;
    }
    __threadfence();
    __syncthreads();
    if (threadIdx.x == 0) {
        asm volatile("st.release.gpu.b32 [%0], %1;" :: "l"(flags + b * NCH + j), "r"(1) : "memory");
    }
    if (threadIdx.x < j) {
        const int* fp = flags + b * NCH + threadIdx.x;
        int f;
        do {
            asm volatile("ld.acquire.gpu.b32 %0, [%1];" : "=r"(f) : "l"(fp) : "memory");
        } while (f == 0);
    }
    __syncthreads();

    float cy = 0.5f;   // h0 = g(0) = 0.5; same forward order as combine_kernel
    for (int jj = 0; jj < j; jj++) {
        int aj = (b * NCH + jj) * HH + c;
        cy = fmaf(cy, aggF[aj], aggH[aj]);
    }
    SC[c] = cy;
    __syncthreads();

    // ---- phase 3: apply + residual + LN; warp w handles rows 2w, 2w+1 ----
    const int wid = threadIdx.x >> 5, lane = threadIdx.x & 31;
#pragma unroll
    for (int tt = 0; tt < 2; tt++) {
        int t = wid * 2 + tt;
        size_t base = (row0 + t) * HH;
        float4* x4 = (float4*)(x + base);
        const float4* sh4 = (const float4*)(SH + t * HH);
        const float4* sp4 = (const float4*)(SP + t * HH);
        const float4* sc4 = (const float4*)SC;

        float4 v[4];
        float s = 0.f, s2 = 0.f;
#pragma unroll
        for (int r = 0; r < 4; r++) {
            int e = lane + r * 32;
            float4 xv = x4[e], hv = sh4[e], pv = sp4[e], cv = sc4[e];
            v[r].x = fmaf(cv.x, pv.x, hv.x) + xv.x;
            v[r].y = fmaf(cv.y, pv.y, hv.y) + xv.y;
            v[r].z = fmaf(cv.z, pv.z, hv.z) + xv.z;
            v[r].w = fmaf(cv.w, pv.w, hv.w) + xv.w;
            if (writeX) x4[e] = v[r];
            s  += v[r].x + v[r].y + v[r].z + v[r].w;
            s2 += v[r].x * v[r].x + v[r].y * v[r].y + v[r].z * v[r].z + v[r].w * v[r].w;
        }
        ln_tail(v, s, s2, lane, lnw, lnb, hasB, xn, base);
    }
}

// ---------------- host launcher ----------------
extern "C" void kernel_launch(void* const* d_in, const int* in_sizes, int n_in,
                              void* d_out, int out_size) {
    const int*   ids   = (const int*)d_in[0];
    const float* emb   = (const float*)d_in[1];
    const float* Ws    = (const float*)d_in[2];
    const float* bs    = (const float*)d_in[3];
    const float* ln_w  = (const float*)d_in[4];
    const float* ln_b  = (const float*)d_in[5];
    const float* fln_w = (const float*)d_in[6];
    const float* fc_w  = (const float*)d_in[7];
    const float* fc_b  = (const float*)d_in[8];
    float* out = (float*)d_out;

    float *px, *pgates, *paggF, *paggH;
    int* pflags;
    __half *pxn, *pwsh, *pfch;
    cudaGetSymbolAddress((void**)&px,     g_x);
    cudaGetSymbolAddress((void**)&pgates, g_gates);
    cudaGetSymbolAddress((void**)&paggF,  g_aggF);
    cudaGetSymbolAddress((void**)&paggH,  g_aggH);
    cudaGetSymbolAddress((void**)&pflags, g_flags);
    cudaGetSymbolAddress((void**)&pxn,    g_xn);
    cudaGetSymbolAddress((void**)&pwsh,   g_wsh);
    cudaGetSymbolAddress((void**)&pfch,   g_fch);

    cudaFuncSetAttribute(gemm_mma<false>, cudaFuncAttributeMaxDynamicSharedMemorySize, GSMEM_TOTAL);
    cudaFuncSetAttribute(gemm_mma<true>,  cudaFuncAttributeMaxDynamicSharedMemorySize, GSMEM_TOTAL);
    cudaFuncSetAttribute(scan_fused_kernel, cudaFuncAttributeMaxDynamicSharedMemorySize, SCAN_SMEM);

    clear_flags_kernel<<<1, LL * BB * NCH>>>(pflags);

    // weight conversions
    {
        int n4 = LL * GG * HH / 4;
        convert_kernel<<<(n4 + 255) / 256, 256>>>(Ws, pwsh, n4);
        int m4 = VV * HH / 4;
        convert_kernel<<<(m4 + 255) / 256, 256>>>(fc_w, pfch, m4);
    }

    // embed + LN of layer 0
    embed_ln_kernel<<<RR / 8, 256>>>(ids, emb, px, pxn, ln_w, ln_b);

    for (int l = 0; l < LL; l++) {
        dim3 ggrid(GG / 128, RR / 128);
        gemm_mma<false><<<ggrid, 128, GSMEM_TOTAL>>>(pxn, pwsh + (size_t)l * GG * HH,
                                                     bs + l * GG, pgates, GG);

        dim3 sgrid(NCH, BB);
        if (l + 1 < LL) {
            scan_fused_kernel<<<sgrid, 512, SCAN_SMEM>>>(
                pgates, px, pxn, ln_w + (l + 1) * HH, ln_b + (l + 1) * HH, 1, 1,
                paggF, paggH, pflags + l * BB * NCH);
        } else {
            scan_fused_kernel<<<sgrid, 512, SCAN_SMEM>>>(
                pgates, px, pxn, fln_w, nullptr, 0, 0,
                paggF, paggH, pflags + l * BB * NCH);
        }
    }

    dim3 fgrid(VV / 128, RR / 128);
    gemm_mma<true><<<fgrid, 128, GSMEM_TOTAL>>>(pxn, pfch, fc_b, out, VV);
}

// round 9
// speedup vs baseline: 1.0050x; 1.0050x over previous
#include <cuda_runtime.h>
#include <cuda_fp16.h>
#include <cstdint>

// Problem constants
#define BB 2
#define SS 2048
#define VV 32000
#define HH 512
#define GG 1536
#define LL 3
#define RR (BB*SS)
#define NCH 64
#define CL  (SS/NCH)   // 32
#define KDIM 512

// ---------------- scratch ----------------
__device__ __align__(128) float g_x[RR * HH];
__device__ __align__(128) float g_gates[RR * GG];
__device__ __align__(128) float g_aggF[BB * NCH * HH];
__device__ __align__(128) float g_aggH[BB * NCH * HH];
__device__ __align__(128) float g_carry[BB * NCH * HH];
__device__ __align__(128) __half g_xn[RR * HH];
__device__ __align__(128) __half g_wsh[LL * GG * HH];
__device__ __align__(128) __half g_fch[(size_t)VV * HH];

// ---------------- helpers ----------------
__device__ __forceinline__ uint32_t smem_u32(const void* p) {
    uint32_t a;
    asm("{ .reg .u64 t; cvta.to.shared.u64 t, %1; cvt.u32.u64 %0, t; }" : "=r"(a) : "l"(p));
    return a;
}
__device__ __forceinline__ void ldsm4(uint32_t* r, uint32_t addr) {
    asm volatile("ldmatrix.sync.aligned.m8n8.x4.shared.b16 {%0,%1,%2,%3}, [%4];"
        : "=r"(r[0]), "=r"(r[1]), "=r"(r[2]), "=r"(r[3]) : "r"(addr));
}
__device__ __forceinline__ void mma16816(float* d, const uint32_t* a, const uint32_t* b) {
    asm volatile("mma.sync.aligned.m16n8k16.row.col.f32.f16.f16.f32 "
        "{%0,%1,%2,%3}, {%4,%5,%6,%7}, {%8,%9}, {%0,%1,%2,%3};"
        : "+f"(d[0]), "+f"(d[1]), "+f"(d[2]), "+f"(d[3])
        : "r"(a[0]), "r"(a[1]), "r"(a[2]), "r"(a[3]), "r"(b[0]), "r"(b[1]));
}
__device__ __forceinline__ void cp16(uint32_t dst, const void* src) {
    asm volatile("cp.async.cg.shared.global [%0], [%1], 16;" :: "r"(dst), "l"(src));
}

// ---------------- fp16 tensor-core GEMM (R6 config: best measured) ----------------
// CTA tile 128x128, 4 warps (2x2), warp tile 64x64, K staged 64, 3-stage cp.async.
#define STB (32 * 1024)
#define NSTAGE 3
#define GSMEM_TOTAL (NSTAGE * STB)

template<bool STREAM>
__global__ __launch_bounds__(128, 2) void gemm_mma(
    const __half* __restrict__ A, const __half* __restrict__ B,
    const float* __restrict__ bias, float* __restrict__ C, int N)
{
    extern __shared__ char smem[];
    const uint32_t sb = smem_u32(smem);
    const int tid = threadIdx.x;
    const int wid = tid >> 5, lane = tid & 31;
    const int m0 = blockIdx.y * 128, n0 = blockIdx.x * 128;
    const int wm = wid & 1, wn = wid >> 1;

    const char* baseA = (const char*)A + (size_t)m0 * (KDIM * 2);
    const char* baseB = (const char*)B + (size_t)n0 * (KDIM * 2);

    float acc[4][8][4];
#pragma unroll
    for (int i = 0; i < 4; i++)
#pragma unroll
        for (int j = 0; j < 8; j++)
#pragma unroll
            for (int q = 0; q < 4; q++) acc[i][j][q] = 0.f;

    auto load_stage = [&](int kc, int buf) {
        const int kb = kc * 128;
        const uint32_t sp = sb + buf * STB;
#pragma unroll
        for (int it = 0; it < 16; it++) {
            int idx = tid + it * 128;
            int r = idx >> 3, c = idx & 7;
            const char* src; uint32_t roff; int lr;
            if (r < 128) { src = baseA; roff = 0;     lr = r; }
            else         { src = baseB; roff = 16384; lr = r - 128; }
            const char* g = src + (size_t)lr * (KDIM * 2) + kb + c * 16;
            uint32_t bo = (uint32_t)(lr * 128 + c * 16);
            bo ^= (bo >> 3) & 0x70;
            cp16(sp + roff + bo, g);
        }
        asm volatile("cp.async.commit_group;" ::: "memory");
    };

    const int quad = lane >> 3, r8 = lane & 7;

    load_stage(0, 0);
    load_stage(1, 1);

    for (int kc = 0; kc < 8; kc++) {
        if (kc < 7) {
            asm volatile("cp.async.wait_group 1;" ::: "memory");
        } else {
            asm volatile("cp.async.wait_group 0;" ::: "memory");
        }
        __syncthreads();

        const uint32_t sp = sb + (kc % NSTAGE) * STB;
#pragma unroll
        for (int ks = 0; ks < 4; ks++) {
            const int colA = ks * 32 + (quad >> 1) * 16;
            const int colB = ks * 32 + (quad & 1) * 16;

            uint32_t af[4][4];
#pragma unroll
            for (int i = 0; i < 4; i++) {
                int row = wm * 64 + i * 16 + r8 + (quad & 1) * 8;
                uint32_t bo = (uint32_t)(row * 128 + colA);
                bo ^= (bo >> 3) & 0x70;
                ldsm4(af[i], sp + bo);
            }
            uint32_t bf[4][4];
#pragma unroll
            for (int j4 = 0; j4 < 4; j4++) {
                int row = wn * 64 + j4 * 16 + r8 + (quad >> 1) * 8;
                uint32_t bo = (uint32_t)(row * 128 + colB);
                bo ^= (bo >> 3) & 0x70;
                ldsm4(bf[j4], sp + 16384 + bo);
            }
#pragma unroll
            for (int i = 0; i < 4; i++)
#pragma unroll
                for (int j = 0; j < 8; j++)
                    mma16816(acc[i][j], af[i], &bf[j >> 1][(j & 1) * 2]);
        }

        if (kc + 2 < 8) load_stage(kc + 2, (kc + 2) % NSTAGE);
    }

    const int tq = lane >> 2, tr = lane & 3;
#pragma unroll
    for (int i = 0; i < 4; i++) {
        int mrow = m0 + wm * 64 + i * 16;
#pragma unroll
        for (int j = 0; j < 8; j++) {
            int col = n0 + wn * 64 + j * 8 + tr * 2;
            float b0 = __ldg(bias + col), b1 = __ldg(bias + col + 1);
            float2 v0 = { acc[i][j][0] + b0, acc[i][j][1] + b1 };
            float2 v1 = { acc[i][j][2] + b0, acc[i][j][3] + b1 };
            float* p0 = C + (size_t)(mrow + tq) * N + col;
            float* p1 = C + (size_t)(mrow + tq + 8) * N + col;
            if (STREAM) { __stcs((float2*)p0, v0); __stcs((float2*)p1, v1); }
            else        { *(float2*)p0 = v0;       *(float2*)p1 = v1; }
        }
    }
}

// ---------------- fp32 -> fp16 convert ----------------
__global__ void convert_kernel(const float* __restrict__ w,
                               __half* __restrict__ o, int n4) {
    int i = blockIdx.x * 256 + threadIdx.x;
    if (i >= n4) return;
    float4 v = __ldg((const float4*)w + i);
    __half2 p0 = { __float2half_rn(v.x), __float2half_rn(v.y) };
    __half2 p1 = { __float2half_rn(v.z), __float2half_rn(v.w) };
    ((__half2*)o)[i * 2] = p0;
    ((__half2*)o)[i * 2 + 1] = p1;
}

// ---------------- gate math (shared by both scan passes) ----------------
__device__ __forceinline__ void gate_step(const float* __restrict__ gp, int c,
                                          float& h, float& p) {
    float fg = gp[c], ig = gp[HH + c], td = gp[2 * HH + c];
    float ea = __expf(-fg), eb = __expf(-ig);
    float inv = __fdividef(1.0f, 2.0f + ea + eb);
    float f = (1.0f + eb) * inv;
    float iv = (1.0f + ea) * inv;
    float g = (td >= 0.f) ? (td + 0.5f) : __fdividef(1.0f, 1.0f + __expf(-td));
    float v = iv * g;
    h = fmaf(f, h, v);
    p *= f;
}

// ---------------- pass 1: aggregates only (no hl/P stores) ----------------
__global__ void gatescan_agg_kernel(const float* __restrict__ gates,
                                    float* __restrict__ aggF, float* __restrict__ aggH) {
    int c = blockIdx.x * 128 + threadIdx.x;
    int j = blockIdx.y;
    int b = blockIdx.z;
    size_t row0 = (size_t)b * SS + (size_t)j * CL;

    float h = 0.f, p = 1.f;
#pragma unroll 4
    for (int t = 0; t < CL; t++)
        gate_step(gates + (row0 + t) * GG, c, h, p);

    int ai = (b * NCH + j) * HH + c;
    aggF[ai] = p;
    aggH[ai] = h;
}

// ---------------- pass 2: sequential combine (bit-identical order) ----------------
__global__ void combine_kernel(const float* __restrict__ aggF,
                               const float* __restrict__ aggH,
                               float* __restrict__ carry) {
    int idx = blockIdx.x * blockDim.x + threadIdx.x;
    if (idx >= BB * HH) return;
    int b = idx / HH, c = idx % HH;
    float cy = 0.5f;
#pragma unroll 8
    for (int j = 0; j < NCH; j++) {
        int ai = (b * NCH + j) * HH + c;
        carry[ai] = cy;
        cy = aggH[ai] + cy * aggF[ai];
    }
}

// ---------------- shared LN tail ----------------
__device__ __forceinline__ void ln_tail(float4* v, float s, float s2, int lane,
                                        const float* __restrict__ w,
                                        const float* __restrict__ bptr, int hasB,
                                        __half* __restrict__ out, size_t rowbase) {
#pragma unroll
    for (int o = 16; o > 0; o >>= 1) {
        s  += __shfl_xor_sync(0xffffffffu, s, o);
        s2 += __shfl_xor_sync(0xffffffffu, s2, o);
    }
    float mean = s * (1.f / HH);
    float var  = s2 * (1.f / HH) - mean * mean;
    float rs = rsqrtf(var + 1e-5f);

    __half2* oh = (__half2*)(out + rowbase);
    const float4* w4 = (const float4*)w;
    const float4* b4 = (const float4*)bptr;
#pragma unroll
    for (int r = 0; r < 4; r++) {
        float4 ww = w4[lane + r * 32];
        float4 o;
        o.x = (v[r].x - mean) * rs * ww.x;
        o.y = (v[r].y - mean) * rs * ww.y;
        o.z = (v[r].z - mean) * rs * ww.z;
        o.w = (v[r].w - mean) * rs * ww.w;
        if (hasB) {
            float4 bb = b4[lane + r * 32];
            o.x += bb.x; o.y += bb.y; o.z += bb.z; o.w += bb.w;
        }
        __half2 p0 = { __float2half_rn(o.x), __float2half_rn(o.y) };
        __half2 p1 = { __float2half_rn(o.z), __float2half_rn(o.w) };
        int e2 = (lane + r * 32) * 2;
        oh[e2] = p0; oh[e2 + 1] = p1;
    }
}

// ---------------- fused embedding gather + LN0 ----------------
__global__ __launch_bounds__(256) void embed_ln_kernel(
    const int* __restrict__ ids, const float* __restrict__ emb,
    float* __restrict__ x, __half* __restrict__ xn,
    const float* __restrict__ w, const float* __restrict__ bptr) {
    int gw = (blockIdx.x * 256 + threadIdx.x) >> 5;
    int lane = threadIdx.x & 31;
    int id = __ldg(ids + gw);
    const float4* src = (const float4*)(emb + (size_t)id * HH);
    float4* xr = (float4*)(x + (size_t)gw * HH);

    float4 v[4];
    float s = 0.f, s2 = 0.f;
#pragma unroll
    for (int r = 0; r < 4; r++) {
        v[r] = src[lane + r * 32];
        xr[lane + r * 32] = v[r];
        s  += v[r].x + v[r].y + v[r].z + v[r].w;
        s2 += v[r].x * v[r].x + v[r].y * v[r].y + v[r].z * v[r].z + v[r].w * v[r].w;
    }
    ln_tail(v, s, s2, lane, w, bptr, 1, xn, (size_t)gw * HH);
}

// ---------------- pass 3: recompute local scan + apply carry + residual + LN ----
// grid (NCH, BB), 512 threads. smem: SH[CL*HH] + SP[CL*HH] + SC[HH] = 130KB.
#define SCAN_SMEM ((2 * CL * HH + HH) * 4)

__global__ __launch_bounds__(512) void scan_apply_ln_kernel(
    const float* __restrict__ gates,
    const float* __restrict__ carry,
    float* __restrict__ x, __half* __restrict__ xn,
    const float* __restrict__ lnw, const float* __restrict__ lnb,
    int hasB, int writeX)
{
    extern __shared__ char smem[];
    float* SH = (float*)smem;            // [CL][HH] local h
    float* SP = SH + CL * HH;            // [CL][HH] local cumprod f
    float* SC = SP + CL * HH;            // [HH] carry per channel

    const int c = threadIdx.x;           // channel
    const int j = blockIdx.x;            // chunk
    const int b = blockIdx.y;            // batch
    const size_t row0 = (size_t)b * SS + (size_t)j * CL;

    // load carry for this chunk (written by combine_kernel)
    SC[c] = carry[(size_t)(b * NCH + j) * HH + c];

    // recompute local scan into smem (identical math/order to gatescan_agg)
    float h = 0.f, p = 1.f;
#pragma unroll 4
    for (int t = 0; t < CL; t++) {
        gate_step(gates + (row0 + t) * GG, c, h, p);
        SH[t * HH + c] = h;
        SP[t * HH + c] = p;
    }
    __syncthreads();

    // apply + residual + LN; warp w handles rows 2w, 2w+1
    const int wid = threadIdx.x >> 5, lane = threadIdx.x & 31;
#pragma unroll
    for (int tt = 0; tt < 2; tt++) {
        int t = wid * 2 + tt;
        size_t base = (row0 + t) * HH;
        float4* x4 = (float4*)(x + base);
        const float4* sh4 = (const float4*)(SH + t * HH);
        const float4* sp4 = (const float4*)(SP + t * HH);
        const float4* sc4 = (const float4*)SC;

        float4 v[4];
        float s = 0.f, s2 = 0.f;
#pragma unroll
        for (int r = 0; r < 4; r++) {
            int e = lane + r * 32;
            float4 xv = x4[e], hv = sh4[e], pv = sp4[e], cv = sc4[e];
            v[r].x = fmaf(cv.x, pv.x, hv.x) + xv.x;
            v[r].y = fmaf(cv.y, pv.y, hv.y) + xv.y;
            v[r].z = fmaf(cv.z, pv.z, hv.z) + xv.z;
            v[r].w = fmaf(cv.w, pv.w, hv.w) + xv.w;
            if (writeX) x4[e] = v[r];
            s  += v[r].x + v[r].y + v[r].z + v[r].w;
            s2 += v[r].x * v[r].x + v[r].y * v[r].y + v[r].z * v[r].z + v[r].w * v[r].w;
        }
        ln_tail(v, s, s2, lane, lnw, lnb, hasB, xn, base);
    }
}

// ---------------- host launcher ----------------
extern "C" void kernel_launch(void* const* d_in, const int* in_sizes, int n_in,
                              void* d_out, int out_size) {
    const int*   ids   = (const int*)d_in[0];
    const float* emb   = (const float*)d_in[1];
    const float* Ws    = (const float*)d_in[2];
    const float* bs    = (const float*)d_in[3];
    const float* ln_w  = (const float*)d_in[4];
    const float* ln_b  = (const float*)d_in[5];
    const float* fln_w = (const float*)d_in[6];
    const float* fc_w  = (const float*)d_in[7];
    const float* fc_b  = (const float*)d_in[8];
    float* out = (float*)d_out;

    float *px, *pgates, *paggF, *paggH, *pcarry;
    __half *pxn, *pwsh, *pfch;
    cudaGetSymbolAddress((void**)&px,     g_x);
    cudaGetSymbolAddress((void**)&pgates, g_gates);
    cudaGetSymbolAddress((void**)&paggF,  g_aggF);
    cudaGetSymbolAddress((void**)&paggH,  g_aggH);
    cudaGetSymbolAddress((void**)&pcarry, g_carry);
    cudaGetSymbolAddress((void**)&pxn,    g_xn);
    cudaGetSymbolAddress((void**)&pwsh,   g_wsh);
    cudaGetSymbolAddress((void**)&pfch,   g_fch);

    cudaFuncSetAttribute(gemm_mma<false>, cudaFuncAttributeMaxDynamicSharedMemorySize, GSMEM_TOTAL);
    cudaFuncSetAttribute(gemm_mma<true>,  cudaFuncAttributeMaxDynamicSharedMemorySize, GSMEM_TOTAL);
    cudaFuncSetAttribute(scan_apply_ln_kernel, cudaFuncAttributeMaxDynamicSharedMemorySize, SCAN_SMEM);

    // weight conversions
    {
        int n4 = LL * GG * HH / 4;
        convert_kernel<<<(n4 + 255) / 256, 256>>>(Ws, pwsh, n4);
        int m4 = VV * HH / 4;
        convert_kernel<<<(m4 + 255) / 256, 256>>>(fc_w, pfch, m4);
    }

    // embed + LN of layer 0
    embed_ln_kernel<<<RR / 8, 256>>>(ids, emb, px, pxn, ln_w, ln_b);

    for (int l = 0; l < LL; l++) {
        dim3 ggrid(GG / 128, RR / 128);
        gemm_mma<false><<<ggrid, 128, GSMEM_TOTAL>>>(pxn, pwsh + (size_t)l * GG * HH,
                                                     bs + l * GG, pgates, GG);

        dim3 agrid(HH / 128, NCH, BB);
        gatescan_agg_kernel<<<agrid, 128>>>(pgates, paggF, paggH);
        combine_kernel<<<(BB * HH + 255) / 256, 256>>>(paggF, paggH, pcarry);

        dim3 sgrid(NCH, BB);
        if (l + 1 < LL) {
            scan_apply_ln_kernel<<<sgrid, 512, SCAN_SMEM>>>(
                pgates, pcarry, px, pxn,
                ln_w + (l + 1) * HH, ln_b + (l + 1) * HH, 1, 1);
        } else {
            scan_apply_ln_kernel<<<sgrid, 512, SCAN_SMEM>>>(
                pgates, pcarry, px, pxn, fln_w, nullptr, 0, 0);
        }
    }

    dim3 fgrid(VV / 128, RR / 128);
    gemm_mma<true><<<fgrid, 128, GSMEM_TOTAL>>>(pxn, pfch, fc_b, out, VV);
}